// round 7
// baseline (speedup 1.0000x reference)
#include <cuda_runtime.h>

// RNNModel: 2-layer tanh RNN + FC, B=2048, T=512, I=8, H=64.
// R6: R5 pipelined design + 2 batch elements per warp (weights shared in regs).
//  - 1 block = 128 threads = 4 warps = 2 batch elements.
//  - lane = (ks, jl): ks = lane>>4 (k half), jl = lane&15; j = warp*16 + jl.
//  - Half-k weight rows in registers (96 regs), REUSED for both elements.
//  - Two independent accumulator chains per warp -> latency hiding.
//  - Layer 1 lags one step -> ONE __syncthreads per step (covers both elements).
//  - t-loop unrolled x2 with compile-time buffer parity; x via pointer walk.
//  - tanh = 1 - 2/(exp2(2x*log2e)+1), unclamped (limits give +-1 exactly).

#define TT 512
#define HH 64
#define NTHREADS 128
#define BB 2048
#define EPB 2                // elements per block (per warp)
#define FULLMASK 0xffffffffu
#define HROW 72              // 64 + skew pad; half0 at [0,32), half1 at [36,68)

typedef unsigned long long ull;

__device__ __forceinline__ ull ffma2(ull a, ull b, ull c) {
    ull d; asm("fma.rn.f32x2 %0, %1, %2, %3;" : "=l"(d) : "l"(a), "l"(b), "l"(c)); return d;
}
__device__ __forceinline__ ull fadd2(ull a, ull b) {
    ull d; asm("add.rn.f32x2 %0, %1, %2;" : "=l"(d) : "l"(a), "l"(b)); return d;
}
__device__ __forceinline__ float hsum4(ull a0, ull a1, ull a2, ull a3) {
    ull s = fadd2(fadd2(a0, a1), fadd2(a2, a3));
    float2 f; asm("mov.b64 {%0, %1}, %2;" : "=f"(f.x), "=f"(f.y) : "l"(s));
    return f.x + f.y;
}
__device__ __forceinline__ float fast_tanh(float x) {
    float e; asm("ex2.approx.f32 %0, %1;" : "=f"(e) : "f"(x * 2.8853900817779268f));
    float r; asm("rcp.approx.f32 %0, %1;" : "=f"(r) : "f"(e + 1.f));
    return fmaf(-2.f, r, 1.f);
}

__global__ void __launch_bounds__(NTHREADS, 2)
rnn_pipe3_kernel(const float* __restrict__ x,
                 const float* __restrict__ W_ih0,
                 const float* __restrict__ W_hh0,
                 const float* __restrict__ b_ih0,
                 const float* __restrict__ b_hh0,
                 const float* __restrict__ W_ih1,
                 const float* __restrict__ W_hh1,
                 const float* __restrict__ b_ih1,
                 const float* __restrict__ b_hh1,
                 const float* __restrict__ fc_w,
                 const float* __restrict__ fc_b,
                 float* __restrict__ out)
{
    __shared__ float h0buf[2][EPB][HROW];   // [parity][element][h]
    __shared__ float h1buf[2][EPB][HROW];
    __shared__ float sfc[EPB][4];

    const int tid  = threadIdx.x;
    const int warp = tid >> 5;
    const int lane = tid & 31;
    const int jl   = lane & 15;
    const int ks   = lane >> 4;              // k half
    const int j    = warp * 16 + jl;
    const int jidx = j + ((j >> 5) << 2);    // skewed store index
    const int khoff = ks * 36;               // skewed read offset (floats)
    const int e0   = blockIdx.x * EPB;

    // Zero h1 buffers (h1[-1] read at i=1; other buffer written before read).
    for (int i = tid; i < 2 * EPB * HROW; i += NTHREADS)
        ((float*)h1buf)[i] = 0.f;

    // ---- Per-lane half-k weight rows in registers (shared by both elements) ----
    ull whh0h[16], wih1h[16], whh1h[16], wih0r[4];
    {
        const ulonglong2* p = (const ulonglong2*)(W_hh0 + j * HH + ks * 32);
        #pragma unroll
        for (int i = 0; i < 8; i++) { ulonglong2 v = p[i]; whh0h[2*i] = v.x; whh0h[2*i+1] = v.y; }
    }
    {
        const ulonglong2* p = (const ulonglong2*)(W_ih1 + j * HH + ks * 32);
        #pragma unroll
        for (int i = 0; i < 8; i++) { ulonglong2 v = p[i]; wih1h[2*i] = v.x; wih1h[2*i+1] = v.y; }
    }
    {
        const ulonglong2* p = (const ulonglong2*)(W_hh1 + j * HH + ks * 32);
        #pragma unroll
        for (int i = 0; i < 8; i++) { ulonglong2 v = p[i]; whh1h[2*i] = v.x; whh1h[2*i+1] = v.y; }
    }
    {
        const ulonglong2* p = (const ulonglong2*)(W_ih0 + j * 8);  // k 0..7 (half 0)
        ulonglong2 v = p[0]; wih0r[0] = v.x; wih0r[1] = v.y;
        v = p[1];            wih0r[2] = v.x; wih0r[3] = v.y;
    }
    if (ks == 1) { wih0r[0] = 0; wih0r[1] = 0; wih0r[2] = 0; wih0r[3] = 0; }

    const float bv0 = b_ih0[j] + b_hh0[j];
    const float bv1 = b_ih1[j] + b_hh1[j];
    float fcw = fc_w[j];
    if (ks == 1) fcw = 0.f;                  // avoid double-count in FC reduce

    // Hoisted skew-baked pointers.
    const ulonglong2 *rp00[EPB], *rp01[EPB], *rp10[EPB], *rp11[EPB];
    float *wp00[EPB], *wp01[EPB], *wp10[EPB], *wp11[EPB];
    #pragma unroll
    for (int el = 0; el < EPB; el++) {
        rp00[el] = (const ulonglong2*)(&h0buf[0][el][khoff]);
        rp01[el] = (const ulonglong2*)(&h0buf[1][el][khoff]);
        rp10[el] = (const ulonglong2*)(&h1buf[0][el][khoff]);
        rp11[el] = (const ulonglong2*)(&h1buf[1][el][khoff]);
        wp00[el] = h0buf[0][el];  wp01[el] = h0buf[1][el];
        wp10[el] = h1buf[0][el];  wp11[el] = h1buf[1][el];
    }

    __syncthreads();

    const ulonglong2* xp[EPB];
    ulonglong2 xa[EPB], xb[EPB];
    #pragma unroll
    for (int el = 0; el < EPB; el++) {
        xp[el] = (const ulonglong2*)(x + (size_t)(e0 + el) * TT * 8);
        xa[el] = xp[el][0]; xb[el] = xp[el][1];
    }

    float h1n[EPB];

    // ---- Peel i=0: h0[0] = tanh(bv0 + x0.Wih0); store to parity-0 buffer ----
    #pragma unroll
    for (int el = 0; el < EPB; el++) {
        ull a0 = ffma2(xa[el].x, wih0r[0], 0ull);
        ull a1 = ffma2(xa[el].y, wih0r[1], 0ull);
        ull a2 = ffma2(xb[el].x, wih0r[2], 0ull);
        ull a3 = ffma2(xb[el].y, wih0r[3], 0ull);
        float s0 = hsum4(a0, a1, a2, a3);
        s0 += __shfl_xor_sync(FULLMASK, s0, 16);
        float h0n = fast_tanh(bv0 + s0);
        if (ks == 0) wp00[el][jidx] = h0n;
    }
    __syncthreads();
    #pragma unroll
    for (int el = 0; el < EPB; el++) {
        xa[el] = xp[el][2]; xb[el] = xp[el][3];
        xp[el] += 4;                            // next needed: x[i=2]
    }

    // Body: per element, compute h0[i] (from H0R) and h1[i-1] (from H0R, H1R);
    // store to H0W/H1W; ONE barrier for both elements.
#define STEP_BODY(H0R, H1R, H0W, H1W, PF)                                        \
    {                                                                            \
        _Pragma("unroll")                                                        \
        for (int el = 0; el < EPB; el++) {                                       \
            ull a0 = ffma2(xa[el].x, wih0r[0], 0ull);                            \
            ull a1 = ffma2(xa[el].y, wih0r[1], 0ull);                            \
            ull a2 = ffma2(xb[el].x, wih0r[2], 0ull);                            \
            ull a3 = ffma2(xb[el].y, wih0r[3], 0ull);                            \
            ull c0 = 0, c1 = 0, c2 = 0, c3 = 0;                                  \
            ulonglong2 nxa, nxb;                                                 \
            if (PF) { nxa = xp[el][0]; nxb = xp[el][1]; xp[el] += 2; }           \
            _Pragma("unroll")                                                    \
            for (int q = 0; q < 8; q++) {                                        \
                ulonglong2 hv = H0R[el][q];                                      \
                if ((q & 1) == 0) {                                              \
                    a0 = ffma2(hv.x, whh0h[2*q], a0); a1 = ffma2(hv.y, whh0h[2*q+1], a1); \
                    c0 = ffma2(hv.x, wih1h[2*q], c0); c1 = ffma2(hv.y, wih1h[2*q+1], c1); \
                } else {                                                         \
                    a2 = ffma2(hv.x, whh0h[2*q], a2); a3 = ffma2(hv.y, whh0h[2*q+1], a3); \
                    c2 = ffma2(hv.x, wih1h[2*q], c2); c3 = ffma2(hv.y, wih1h[2*q+1], c3); \
                }                                                                \
            }                                                                    \
            _Pragma("unroll")                                                    \
            for (int q = 0; q < 8; q++) {                                        \
                ulonglong2 hv = H1R[el][q];                                      \
                if ((q & 1) == 0) {                                              \
                    c0 = ffma2(hv.x, whh1h[2*q], c0); c1 = ffma2(hv.y, whh1h[2*q+1], c1); \
                } else {                                                         \
                    c2 = ffma2(hv.x, whh1h[2*q], c2); c3 = ffma2(hv.y, whh1h[2*q+1], c3); \
                }                                                                \
            }                                                                    \
            float s0 = hsum4(a0, a1, a2, a3);                                    \
            s0 += __shfl_xor_sync(FULLMASK, s0, 16);                             \
            float h0n = fast_tanh(bv0 + s0);                                     \
            float s1 = hsum4(c0, c1, c2, c3);                                    \
            s1 += __shfl_xor_sync(FULLMASK, s1, 16);                             \
            h1n[el] = fast_tanh(bv1 + s1);                                       \
            if (ks == 0) { H0W[el][jidx] = h0n; H1W[el][jidx] = h1n[el]; }       \
            if (PF) { xa[el] = nxa; xb[el] = nxb; }                              \
        }                                                                        \
        __syncthreads();                                                         \
    }

    // i = 1..510 as 255 unrolled pairs (odd parity, then even parity).
    for (int iu = 0; iu < 255; iu++) {
        STEP_BODY(rp00, rp11, wp01, wp10, 1);  // i odd:  h0r=buf0, h1r=buf1 -> buf1, buf0
        STEP_BODY(rp01, rp10, wp00, wp11, 1);  // i even: h0r=buf1, h1r=buf0 -> buf0, buf1
    }
    // i = 511 (odd), no prefetch.
    STEP_BODY(rp00, rp11, wp01, wp10, 0);

    // ---- Tail: h1[511] from h0[511] (buf1) and h1[510] (buf0) ----
    #pragma unroll
    for (int el = 0; el < EPB; el++) {
        ull c0 = 0, c1 = 0, c2 = 0, c3 = 0;
        #pragma unroll
        for (int q = 0; q < 8; q++) {
            ulonglong2 hv = rp01[el][q];
            if ((q & 1) == 0) { c0 = ffma2(hv.x, wih1h[2*q], c0); c1 = ffma2(hv.y, wih1h[2*q+1], c1); }
            else              { c2 = ffma2(hv.x, wih1h[2*q], c2); c3 = ffma2(hv.y, wih1h[2*q+1], c3); }
        }
        #pragma unroll
        for (int q = 0; q < 8; q++) {
            ulonglong2 hv = rp10[el][q];
            if ((q & 1) == 0) { c0 = ffma2(hv.x, whh1h[2*q], c0); c1 = ffma2(hv.y, whh1h[2*q+1], c1); }
            else              { c2 = ffma2(hv.x, whh1h[2*q], c2); c3 = ffma2(hv.y, whh1h[2*q+1], c3); }
        }
        float s1 = hsum4(c0, c1, c2, c3);
        s1 += __shfl_xor_sync(FULLMASK, s1, 16);
        h1n[el] = fast_tanh(bv1 + s1);
    }

    // ---- FC: out[e] = sum_j h1_last[j] * fc_w[j] + fc_b ----
    #pragma unroll
    for (int el = 0; el < EPB; el++) {
        float v = h1n[el] * fcw;             // fcw==0 on ks=1 lanes
        #pragma unroll
        for (int off = 16; off > 0; off >>= 1)
            v += __shfl_xor_sync(FULLMASK, v, off);
        if (lane == 0) sfc[el][warp] = v;
    }
    __syncthreads();
    if (tid < EPB)
        out[e0 + tid] = sfc[tid][0] + sfc[tid][1] + sfc[tid][2] + sfc[tid][3] + fc_b[0];
#undef STEP_BODY
}

extern "C" void kernel_launch(void* const* d_in, const int* in_sizes, int n_in,
                              void* d_out, int out_size)
{
    const float* x     = (const float*)d_in[0];
    const float* W_ih0 = (const float*)d_in[1];
    const float* W_hh0 = (const float*)d_in[2];
    const float* b_ih0 = (const float*)d_in[3];
    const float* b_hh0 = (const float*)d_in[4];
    const float* W_ih1 = (const float*)d_in[5];
    const float* W_hh1 = (const float*)d_in[6];
    const float* b_ih1 = (const float*)d_in[7];
    const float* b_hh1 = (const float*)d_in[8];
    const float* fc_w  = (const float*)d_in[9];
    const float* fc_b  = (const float*)d_in[10];
    float* out = (float*)d_out;

    dim3 grid(BB / EPB);    // 1024 blocks, two batch elements each
    dim3 block(NTHREADS);   // 128 threads = 4 warps
    rnn_pipe3_kernel<<<grid, block>>>(
        x, W_ih0, W_hh0, b_ih0, b_hh0,
        W_ih1, W_hh1, b_ih1, b_hh1,
        fc_w, fc_b, out);
}